// round 15
// baseline (speedup 1.0000x reference)
#include <cuda_runtime.h>
#include <cuda_bf16.h>
#include <math.h>
#include <stdint.h>

#define B_  2
#define L_  2048
#define D_  1024
#define H_  16
#define DH_ 64
#define R_  (B_ * L_)
#define D3_ (3 * D_)

// ---------------- scratch ----------------------------------------------------
__device__ float g_qkv[(size_t)R_ * D3_];                  // fp32 q/k (gemm out)
__device__ __nv_bfloat16 g_hh[(size_t)R_ * D_];            // LN1 out hi/lo
__device__ __nv_bfloat16 g_hl[(size_t)R_ * D_];
__device__ __nv_bfloat16 g_qh[(size_t)B_ * H_ * L_ * DH_]; // head-major
__device__ __nv_bfloat16 g_ql[(size_t)B_ * H_ * L_ * DH_];
__device__ __nv_bfloat16 g_kh[(size_t)B_ * H_ * L_ * DH_];
__device__ __nv_bfloat16 g_kl[(size_t)B_ * H_ * L_ * DH_];
__device__ __nv_bfloat16 g_vh[(size_t)B_ * H_ * L_ * DH_];
__device__ __nv_bfloat16 g_vl[(size_t)B_ * H_ * L_ * DH_];
__device__ __nv_bfloat16 g_ch[(size_t)B_ * H_ * L_ * DH_];
__device__ __nv_bfloat16 g_cl[(size_t)B_ * H_ * L_ * DH_];
__device__ __nv_bfloat16 g_wqh[(size_t)D_ * D3_];
__device__ __nv_bfloat16 g_wql[(size_t)D_ * D3_];
__device__ __nv_bfloat16 g_woh[(size_t)D_ * D_];
__device__ __nv_bfloat16 g_wol[(size_t)D_ * D_];
__device__ float g_cos[L_ * 32];
__device__ float g_sin[L_ * 32];

// ---------------- helpers ----------------------------------------------------
__device__ __forceinline__ uint32_t pk(float a, float b) {
    __nv_bfloat162 t = __floats2bfloat162_rn(a, b);
    return *reinterpret_cast<uint32_t*>(&t);
}
__device__ __forceinline__ void hl(float x, float& h, float& l) {
    h = __bfloat162float(__float2bfloat16(x));
    l = x - h;
}
__device__ __forceinline__ void cvt4(float4 v, uint32_t& h01, uint32_t& h23,
                                     uint32_t& l01, uint32_t& l23) {
    float hx, lx, hy, ly, hz, lz, hw, lw;
    hl(v.x, hx, lx); hl(v.y, hy, ly); hl(v.z, hz, lz); hl(v.w, hw, lw);
    h01 = pk(hx, hy); h23 = pk(hz, hw);
    l01 = pk(lx, ly); l23 = pk(lz, lw);
}
__device__ __forceinline__ void ldsm4(uint32_t a, uint32_t& r0, uint32_t& r1,
                                      uint32_t& r2, uint32_t& r3) {
    asm volatile("ldmatrix.sync.aligned.m8n8.x4.shared.b16 {%0,%1,%2,%3},[%4];"
                 : "=r"(r0), "=r"(r1), "=r"(r2), "=r"(r3) : "r"(a));
}
__device__ __forceinline__ void ldsm4t(uint32_t a, uint32_t& r0, uint32_t& r1,
                                       uint32_t& r2, uint32_t& r3) {
    asm volatile("ldmatrix.sync.aligned.m8n8.x4.trans.shared.b16 {%0,%1,%2,%3},[%4];"
                 : "=r"(r0), "=r"(r1), "=r"(r2), "=r"(r3) : "r"(a));
}
__device__ __forceinline__ void mma16(float* acc, const uint32_t* a,
                                      uint32_t b0, uint32_t b1) {
    asm volatile(
        "mma.sync.aligned.m16n8k16.row.col.f32.bf16.bf16.f32 "
        "{%0,%1,%2,%3},{%4,%5,%6,%7},{%8,%9},{%0,%1,%2,%3};"
        : "+f"(acc[0]), "+f"(acc[1]), "+f"(acc[2]), "+f"(acc[3])
        : "r"(a[0]), "r"(a[1]), "r"(a[2]), "r"(a[3]), "r"(b0), "r"(b1));
}
// .ca: allocate in L1 so co-resident blocks streaming the same operand hit L1
__device__ __forceinline__ void cpa16(uint32_t dst, const void* src) {
    asm volatile("cp.async.ca.shared.global [%0], [%1], 16;" :: "r"(dst), "l"(src) : "memory");
}
__device__ __forceinline__ void cp_commit() {
    asm volatile("cp.async.commit_group;" ::: "memory");
}
template<int N> __device__ __forceinline__ void cp_wait() {
    asm volatile("cp.async.wait_group %0;" :: "n"(N) : "memory");
}

// ---------------- RoPE table -------------------------------------------------
__global__ void rope_tab_kernel() {
    int l = blockIdx.x;
    int j = threadIdx.x;
    float inv_f = (float)pow(10000.0, -(double)j / 32.0);
    float ang_f = (float)l * inv_f;
    double a = (double)ang_f;
    g_cos[l * 32 + j] = (float)cos(a);
    g_sin[l * 32 + j] = (float)sin(a);
}

// ---------------- weight fp32 -> bf16 hi/lo ----------------------------------
__global__ void __launch_bounds__(256) convw_kernel(const float* __restrict__ w,
                                                    __nv_bfloat16* __restrict__ wh,
                                                    __nv_bfloat16* __restrict__ wl,
                                                    int n4) {
    int i = blockIdx.x * 256 + threadIdx.x;
    if (i >= n4) return;
    float4 v = ((const float4*)w)[i];
    uint32_t h01, h23, l01, l23;
    cvt4(v, h01, h23, l01, l23);
    ((uint2*)wh)[i] = make_uint2(h01, h23);
    ((uint2*)wl)[i] = make_uint2(l01, l23);
}

// ---------------- LN1: writes bf16 hi/lo -------------------------------------
__global__ void __launch_bounds__(256) ln1_kernel(const float* __restrict__ x,
                                                  const float* __restrict__ w,
                                                  const float* __restrict__ b) {
    __shared__ float sa[8], sb[8];
    int row = blockIdx.x;
    int t = threadIdx.x;
    float4 v = ((const float4*)(x + (size_t)row * D_))[t];
    float s  = v.x + v.y + v.z + v.w;
    float ss = v.x * v.x + v.y * v.y + v.z * v.z + v.w * v.w;
#pragma unroll
    for (int o = 16; o > 0; o >>= 1) {
        s  += __shfl_xor_sync(0xffffffffu, s, o);
        ss += __shfl_xor_sync(0xffffffffu, ss, o);
    }
    if ((t & 31) == 0) { sa[t >> 5] = s; sb[t >> 5] = ss; }
    __syncthreads();
    float ts = 0.f, tss = 0.f;
#pragma unroll
    for (int i = 0; i < 8; i++) { ts += sa[i]; tss += sb[i]; }
    float mu  = ts * (1.0f / D_);
    float var = tss * (1.0f / D_) - mu * mu;
    float rs  = rsqrtf(var + 1e-5f);
    float4 wv = ((const float4*)w)[t];
    float4 bv = ((const float4*)b)[t];
    float4 o;
    o.x = (v.x - mu) * rs * wv.x + bv.x;
    o.y = (v.y - mu) * rs * wv.y + bv.y;
    o.z = (v.z - mu) * rs * wv.z + bv.z;
    o.w = (v.w - mu) * rs * wv.w + bv.w;
    uint32_t h01, h23, l01, l23;
    cvt4(o, h01, h23, l01, l23);
    ((uint2*)(g_hh + (size_t)row * D_))[t] = make_uint2(h01, h23);
    ((uint2*)(g_hl + (size_t)row * D_))[t] = make_uint2(l01, l23);
}

// ---------------- q/k LN + RoPE, head-major hi/lo out ------------------------
__global__ void __launch_bounds__(256) qkln_rope_kernel(const float* __restrict__ qw,
                                                        const float* __restrict__ kw) {
    __shared__ float sa[8], sb[8];
    __shared__ float sv[D_];
    int row = blockIdx.x;
    int which = blockIdx.y;          // 0=q, 1=k
    int t = threadIdx.x;
    int bb = row >> 11, l = row & (L_ - 1);

    float* base = g_qkv + (size_t)row * D3_ + which * D_;
    const float* w = which ? kw : qw;

    float4 v = ((const float4*)base)[t];
    float s  = v.x + v.y + v.z + v.w;
    float ss = v.x * v.x + v.y * v.y + v.z * v.z + v.w * v.w;
#pragma unroll
    for (int o = 16; o > 0; o >>= 1) {
        s  += __shfl_xor_sync(0xffffffffu, s, o);
        ss += __shfl_xor_sync(0xffffffffu, ss, o);
    }
    if ((t & 31) == 0) { sa[t >> 5] = s; sb[t >> 5] = ss; }
    __syncthreads();
    float ts = 0.f, tss = 0.f;
#pragma unroll
    for (int i = 0; i < 8; i++) { ts += sa[i]; tss += sb[i]; }
    float mu  = ts * (1.0f / D_);
    float var = tss * (1.0f / D_) - mu * mu;
    float rs  = rsqrtf(var + 1e-5f);
    float4 wv = ((const float4*)w)[t];
    sv[4 * t + 0] = (v.x - mu) * rs * wv.x;
    sv[4 * t + 1] = (v.y - mu) * rs * wv.y;
    sv[4 * t + 2] = (v.z - mu) * rs * wv.z;
    sv[4 * t + 3] = (v.w - mu) * rs * wv.w;
    __syncthreads();

    float res[4];
#pragma unroll
    for (int c = 0; c < 4; c++) {
        int col = 4 * t + c;
        int d = col & 63, dd = d & 31;
        float cs = g_cos[l * 32 + dd];
        float sn = g_sin[l * 32 + dd];
        float y = sv[col];
        res[c] = (d < 32) ? (y * cs - sv[col + 32] * sn)
                          : (y * cs + sv[col - 32] * sn);
    }
    uint32_t h01, h23, l01, l23;
    cvt4(make_float4(res[0], res[1], res[2], res[3]), h01, h23, l01, l23);
    int col = 4 * t, hh = col >> 6, d = col & 63;
    size_t di = (((size_t)(bb * H_ + hh)) * L_ + l) * 64 + d;
    __nv_bfloat16* oh = which ? g_kh : g_qh;
    __nv_bfloat16* ol = which ? g_kl : g_ql;
    *(uint2*)(oh + di) = make_uint2(h01, h23);
    *(uint2*)(ol + di) = make_uint2(l01, l23);
}

// ---------------- bf16x2 GEMM: 128x64 tile, BK=64, 2 stages, 96KB ------------
// stage: Ah 16K | Al 16K | Bh 8K | Bl 8K = 48 KB -> 2 blocks/SM
#define GS_SZ   49152
#define GS_BH   32768
#define GS_BL   40960
#define GEMM_SMEM (2 * GS_SZ)

template<bool HEADMAJ>
__device__ __forceinline__ void g_prefetch(uint32_t base, int c, int tid,
        int m0, int n0, int N,
        const __nv_bfloat16* __restrict__ Ahg, const __nv_bfloat16* __restrict__ Alg,
        const __nv_bfloat16* __restrict__ Bhg, const __nv_bfloat16* __restrict__ Blg) {
    uint32_t sb = base + (c & 1) * GS_SZ;
#pragma unroll
    for (int i = 0; i < 4; i++) {        // A: 128 rows x 8 segs
        int id = tid + i * 256;
        int row = id >> 3, sg = id & 7;
        size_t asrc;
        if (HEADMAJ) {
            int gr = m0 + row;
            int bb = gr >> 11, l = gr & (L_ - 1);
            asrc = (((size_t)(bb * H_ + c)) * L_ + l) * 64 + sg * 8;
        } else {
            asrc = (size_t)(m0 + row) * 1024 + c * 64 + sg * 8;
        }
        uint32_t ad = sb + row * 128 + ((sg * 16) ^ ((row & 7) << 4));
        cpa16(ad,         Ahg + asrc);
        cpa16(ad + 16384, Alg + asrc);
    }
#pragma unroll
    for (int i = 0; i < 2; i++) {        // B: 64 k-rows x 8 segs (rows = 128B)
        int id = tid + i * 256;
        int k = id >> 3, sg = id & 7;
        size_t bsrc = (size_t)(c * 64 + k) * N + n0 + sg * 8;
        uint32_t bd = sb + GS_BH + k * 128 + ((sg * 16) ^ ((k & 7) << 4));
        cpa16(bd,        Bhg + bsrc);
        cpa16(bd + 8192, Blg + bsrc);
    }
    cp_commit();
}

template<bool HEADMAJ, bool VOUT>
__global__ void __launch_bounds__(256) gemm_tc(
        const __nv_bfloat16* __restrict__ Ahg, const __nv_bfloat16* __restrict__ Alg,
        const __nv_bfloat16* __restrict__ Bhg, const __nv_bfloat16* __restrict__ Blg,
        float* __restrict__ C, int N) {
    extern __shared__ __align__(16) char sm[];
    uint32_t base = (uint32_t)__cvta_generic_to_shared(sm);
    int tid = threadIdx.x, wid = tid >> 5, lane = tid & 31;
    int wm = wid >> 1, wn = wid & 1;
    int m0 = blockIdx.y * 128, n0 = blockIdx.x * 64;

    g_prefetch<HEADMAJ>(base, 0, tid, m0, n0, N, Ahg, Alg, Bhg, Blg);

    float acc[2][4][4] = {};
    for (int c = 0; c < 16; c++) {
        if (c + 1 < 16) {
            g_prefetch<HEADMAJ>(base, c + 1, tid, m0, n0, N, Ahg, Alg, Bhg, Blg);
            cp_wait<1>();
        } else {
            cp_wait<0>();
        }
        __syncthreads();
        uint32_t sb = base + (c & 1) * GS_SZ;
#pragma unroll
        for (int ks = 0; ks < 4; ks++) {
            uint32_t ah[2][4], al[2][4];
#pragma unroll
            for (int mt = 0; mt < 2; mt++) {
                int row = wm * 32 + mt * 16 + (lane & 15);
                uint32_t ad = sb + row * 128 +
                              ((ks * 32 + (lane >> 4) * 16) ^ ((row & 7) << 4));
                ldsm4(ad,         ah[mt][0], ah[mt][1], ah[mt][2], ah[mt][3]);
                ldsm4(ad + 16384, al[mt][0], al[mt][1], al[mt][2], al[mt][3]);
            }
#pragma unroll
            for (int np = 0; np < 2; np++) {
                int k = ks * 16 + (lane & 15);
                int ntile = wn * 4 + np * 2 + (lane >> 4);
                uint32_t bd = sb + GS_BH + k * 128 +
                              ((ntile * 16) ^ ((k & 7) << 4));
                uint32_t bh0, bh1, bh2, bh3, bl0, bl1, bl2, bl3;
                ldsm4t(bd,        bh0, bh1, bh2, bh3);
                ldsm4t(bd + 8192, bl0, bl1, bl2, bl3);
#pragma unroll
                for (int mt = 0; mt < 2; mt++) {
                    mma16(acc[mt][np * 2],     ah[mt], bh0, bh1);
                    mma16(acc[mt][np * 2],     al[mt], bh0, bh1);
                    mma16(acc[mt][np * 2],     ah[mt], bl0, bl1);
                    mma16(acc[mt][np * 2 + 1], ah[mt], bh2, bh3);
                    mma16(acc[mt][np * 2 + 1], al[mt], bh2, bh3);
                    mma16(acc[mt][np * 2 + 1], ah[mt], bl2, bl3);
                }
            }
        }
        __syncthreads();   // all warps done with buf (c&1) before it is refilled
    }
    // epilogue
    if (VOUT && n0 >= 2048) {
#pragma unroll
        for (int mt = 0; mt < 2; mt++) {
            int r = m0 + wm * 32 + mt * 16 + (lane >> 2);
            int ccv = (n0 - 2048) + wn * 32 + (lane & 3) * 2;
            int bb = r >> 11, lv = r & (L_ - 1);
#pragma unroll
            for (int nt = 0; nt < 4; nt++) {
                int col = ccv + nt * 8;
                int hh = col >> 6, d = col & 63;
                size_t di = (((size_t)(bb * H_ + hh)) * L_ + lv) * 64 + d;
                float h0, l0, h1, l1, h2, l2, h3, l3;
                hl(acc[mt][nt][0], h0, l0); hl(acc[mt][nt][1], h1, l1);
                hl(acc[mt][nt][2], h2, l2); hl(acc[mt][nt][3], h3, l3);
                *(uint32_t*)(g_vh + di) = pk(h0, h1);
                *(uint32_t*)(g_vl + di) = pk(l0, l1);
                *(uint32_t*)(g_vh + di + (size_t)8 * 64) = pk(h2, h3);
                *(uint32_t*)(g_vl + di + (size_t)8 * 64) = pk(l2, l3);
            }
        }
    } else {
#pragma unroll
        for (int mt = 0; mt < 2; mt++) {
            int r = m0 + wm * 32 + mt * 16 + (lane >> 2);
            int cc = n0 + wn * 32 + (lane & 3) * 2;
#pragma unroll
            for (int nt = 0; nt < 4; nt++) {
                *(float2*)(C + (size_t)r * N + cc + nt * 8) =
                    make_float2(acc[mt][nt][0], acc[mt][nt][1]);
                *(float2*)(C + (size_t)(r + 8) * N + cc + nt * 8) =
                    make_float2(acc[mt][nt][2], acc[mt][nt][3]);
            }
        }
    }
}

// ---------------- flash attention: R9 exact (QK+PV 3-term, P via smem) -------
// smem: Qh 0 | Ql 16384 | Kh 32768 | Kl 40960 | Vh 49152 | Vl 57344 |
//       P 65536 (32768, 256B pitch hi|lo) | kseq 98304
#define ATTN_SMEM 98560

__global__ void __launch_bounds__(256) attn_kernel(const int* __restrict__ seq_id) {
    extern __shared__ __align__(16) char smA[];
    char* Ps = smA + 65536;
    int* kseq = (int*)(smA + 98304);
    uint32_t base = (uint32_t)__cvta_generic_to_shared(smA);
    uint32_t qB = base, kB = base + 32768, vB = base + 49152, pB = base + 65536;

    int qt = blockIdx.x, h = blockIdx.y, b = blockIdx.z;
    int tid = threadIdx.x, wid = tid >> 5, lane = tid & 31;
    int q0 = qt * 128;
    size_t bh = (size_t)(b * H_ + h);
    const int* seqb = seq_id + b * L_;

#pragma unroll
    for (int i = 0; i < 4; i++) {
        int id = tid + i * 256;
        int q = id >> 3, sg = id & 7;
        size_t src = (bh * L_ + q0 + q) * 64 + sg * 8;
        uint32_t ad = qB + q * 128 + ((sg * 16) ^ ((q & 7) << 4));
        cpa16(ad,         g_qh + src);
        cpa16(ad + 16384, g_ql + src);
    }
    cp_commit();

    int qs0 = seqb[q0 + wid * 16 + (lane >> 2)];
    int qs1 = seqb[q0 + wid * 16 + (lane >> 2) + 8];

    int sa = seqb[q0], sb2 = seqb[q0 + 127];
    int lo = 0, hi = L_;
    while (lo < hi) { int mid = (lo + hi) >> 1; if (seqb[mid] < sa) lo = mid + 1; else hi = mid; }
    int klo = lo;
    lo = 0; hi = L_;
    while (lo < hi) { int mid = (lo + hi) >> 1; if (seqb[mid] <= sb2) lo = mid + 1; else hi = mid; }
    int khi = lo;
    int kt0 = klo >> 6, kt1 = (khi - 1) >> 6;

    float O[8][4] = {};
    float m0v = -1e30f, m1v = -1e30f, l0s = 0.f, l1s = 0.f;
    int c0 = (lane & 3) * 2;

    for (int kt = kt0; kt <= kt1; kt++) {
        __syncthreads();
#pragma unroll
        for (int i = 0; i < 2; i++) {
            int id = tid + i * 256;
            int kp = id >> 3, sg = id & 7;
            size_t src = (bh * L_ + kt * 64 + kp) * 64 + sg * 8;
            uint32_t sw = (sg * 16) ^ ((kp & 7) << 4);
            cpa16(kB + kp * 128 + sw,        g_kh + src);
            cpa16(kB + kp * 128 + sw + 8192, g_kl + src);
            cpa16(vB + kp * 128 + sw,        g_vh + src);
            cpa16(vB + kp * 128 + sw + 8192, g_vl + src);
        }
        cp_commit();
        if (tid < 64) kseq[tid] = seqb[kt * 64 + tid];
        cp_wait<0>();
        __syncthreads();

        // S = Q K^T (3-term)
        float S[8][4] = {};
#pragma unroll
        for (int ds = 0; ds < 4; ds++) {
            uint32_t ah[4], al[4];
            int row = wid * 16 + (lane & 15);
            uint32_t ad = qB + row * 128 +
                          ((ds * 32 + (lane >> 4) * 16) ^ ((row & 7) << 4));
            ldsm4(ad,         ah[0], ah[1], ah[2], ah[3]);
            ldsm4(ad + 16384, al[0], al[1], al[2], al[3]);
#pragma unroll
            for (int np = 0; np < 4; np++) {
                int kpos = (np * 2 + (lane >> 4)) * 8 + (lane & 7);
                int dbyte = ds * 32 + ((lane >> 3) & 1) * 16;
                uint32_t kd = kB + kpos * 128 + (dbyte ^ ((kpos & 7) << 4));
                uint32_t bh0, bh1, bh2, bh3, bl0, bl1, bl2, bl3;
                ldsm4(kd,        bh0, bh1, bh2, bh3);
                ldsm4(kd + 8192, bl0, bl1, bl2, bl3);
                mma16(S[np * 2],     ah, bh0, bh1);
                mma16(S[np * 2],     al, bh0, bh1);
                mma16(S[np * 2],     ah, bl0, bl1);
                mma16(S[np * 2 + 1], ah, bh2, bh3);
                mma16(S[np * 2 + 1], al, bh2, bh3);
                mma16(S[np * 2 + 1], ah, bl2, bl3);
            }
        }
        // mask + scale + online softmax
        float mx0 = -1e30f, mx1 = -1e30f;
#pragma unroll
        for (int nt = 0; nt < 8; nt++) {
            int k0 = kseq[nt * 8 + c0], k1 = kseq[nt * 8 + c0 + 1];
            S[nt][0] = (qs0 == k0) ? S[nt][0] * 0.125f : -1e30f;
            S[nt][1] = (qs0 == k1) ? S[nt][1] * 0.125f : -1e30f;
            S[nt][2] = (qs1 == k0) ? S[nt][2] * 0.125f : -1e30f;
            S[nt][3] = (qs1 == k1) ? S[nt][3] * 0.125f : -1e30f;
            mx0 = fmaxf(mx0, fmaxf(S[nt][0], S[nt][1]));
            mx1 = fmaxf(mx1, fmaxf(S[nt][2], S[nt][3]));
        }
        mx0 = fmaxf(mx0, __shfl_xor_sync(0xffffffffu, mx0, 1));
        mx0 = fmaxf(mx0, __shfl_xor_sync(0xffffffffu, mx0, 2));
        mx1 = fmaxf(mx1, __shfl_xor_sync(0xffffffffu, mx1, 1));
        mx1 = fmaxf(mx1, __shfl_xor_sync(0xffffffffu, mx1, 2));
        float mn0 = fmaxf(m0v, mx0), mn1 = fmaxf(m1v, mx1);
        float al0 = __expf(m0v - mn0), al1 = __expf(m1v - mn1);
        m0v = mn0; m1v = mn1;

        int r = wid * 16 + (lane >> 2);
        int r2 = r + 8;
        float rs0 = 0.f, rs1 = 0.f;
#pragma unroll
        for (int nt = 0; nt < 8; nt++) {
            float p00 = (S[nt][0] <= -9e29f) ? 0.f : __expf(S[nt][0] - mn0);
            float p01 = (S[nt][1] <= -9e29f) ? 0.f : __expf(S[nt][1] - mn0);
            float p10 = (S[nt][2] <= -9e29f) ? 0.f : __expf(S[nt][2] - mn1);
            float p11 = (S[nt][3] <= -9e29f) ? 0.f : __expf(S[nt][3] - mn1);
            rs0 += p00 + p01;
            rs1 += p10 + p11;
            int c = nt * 8 + c0;
            float h00, lo00, h01v, lo01, h10, lo10, h11v, lo11;
            hl(p00, h00, lo00); hl(p01, h01v, lo01);
            hl(p10, h10, lo10); hl(p11, h11v, lo11);
            int sw0 = (c * 2) ^ ((r & 7) << 4);
            char* pp = Ps + r * 256;
            *(uint32_t*)(pp + sw0)       = pk(h00, h01v);
            *(uint32_t*)(pp + 128 + sw0) = pk(lo00, lo01);
            int sw2 = (c * 2) ^ ((r2 & 7) << 4);
            char* pp2 = Ps + r2 * 256;
            *(uint32_t*)(pp2 + sw2)       = pk(h10, h11v);
            *(uint32_t*)(pp2 + 128 + sw2) = pk(lo10, lo11);
        }
        rs0 += __shfl_xor_sync(0xffffffffu, rs0, 1);
        rs0 += __shfl_xor_sync(0xffffffffu, rs0, 2);
        rs1 += __shfl_xor_sync(0xffffffffu, rs1, 1);
        rs1 += __shfl_xor_sync(0xffffffffu, rs1, 2);
        l0s = l0s * al0 + rs0;
        l1s = l1s * al1 + rs1;
#pragma unroll
        for (int nt = 0; nt < 8; nt++) {
            O[nt][0] *= al0; O[nt][1] *= al0;
            O[nt][2] *= al1; O[nt][3] *= al1;
        }
        __syncwarp();

        // O += P V (3-term)
#pragma unroll
        for (int ks = 0; ks < 4; ks++) {
            uint32_t ah[4], al[4];
            int row = wid * 16 + (lane & 15);
            uint32_t ad = pB + row * 256 +
                          ((ks * 32 + (lane >> 4) * 16) ^ ((row & 7) << 4));
            ldsm4(ad,       ah[0], ah[1], ah[2], ah[3]);
            ldsm4(ad + 128, al[0], al[1], al[2], al[3]);
#pragma unroll
            for (int np = 0; np < 4; np++) {
                int kpos = ks * 16 + ((lane >> 3) & 1) * 8 + (lane & 7);
                int dtile = np * 2 + (lane >> 4);
                uint32_t vd = vB + kpos * 128 + ((dtile * 16) ^ ((kpos & 7) << 4));
                uint32_t bh0, bh1, bh2, bh3, bl0, bl1, bl2, bl3;
                ldsm4t(vd,        bh0, bh1, bh2, bh3);
                ldsm4t(vd + 8192, bl0, bl1, bl2, bl3);
                mma16(O[np * 2],     ah, bh0, bh1);
                mma16(O[np * 2],     al, bh0, bh1);
                mma16(O[np * 2],     ah, bl0, bl1);
                mma16(O[np * 2 + 1], ah, bh2, bh3);
                mma16(O[np * 2 + 1], al, bh2, bh3);
                mma16(O[np * 2 + 1], ah, bl2, bl3);
            }
        }
    }
    // epilogue: ctx bf16 hi/lo, head-major
    float inv0 = 1.0f / l0s, inv1 = 1.0f / l1s;
    int r0 = q0 + wid * 16 + (lane >> 2);
    size_t ob = (bh * L_ + r0) * 64 + (lane & 3) * 2;
#pragma unroll
    for (int nt = 0; nt < 8; nt++) {
        float v0 = O[nt][0] * inv0, v1 = O[nt][1] * inv0;
        float v2 = O[nt][2] * inv1, v3 = O[nt][3] * inv1;
        float h0, lo0, h1, lo1, h2, lo2, h3, lo3;
        hl(v0, h0, lo0); hl(v1, h1, lo1); hl(v2, h2, lo2); hl(v3, h3, lo3);
        *(uint32_t*)(g_ch + ob + nt * 8) = pk(h0, h1);
        *(uint32_t*)(g_cl + ob + nt * 8) = pk(lo0, lo1);
        *(uint32_t*)(g_ch + ob + (size_t)8 * 64 + nt * 8) = pk(h2, h3);
        *(uint32_t*)(g_cl + ob + (size_t)8 * 64 + nt * 8) = pk(lo2, lo3);
    }
}

// ---------------- launch ------------------------------------------------------
extern "C" void kernel_launch(void* const* d_in, const int* in_sizes, int n_in,
                              void* d_out, int out_size) {
    const float* x    = (const float*)d_in[0];
    const int*   seq  = (const int*)d_in[1];
    const float* ln1w = (const float*)d_in[2];
    const float* ln1b = (const float*)d_in[3];
    const float* wqkv = (const float*)d_in[4];
    const float* qlnw = (const float*)d_in[5];
    const float* klnw = (const float*)d_in[6];
    const float* wout = (const float*)d_in[7];
    float* out = (float*)d_out;

    __nv_bfloat16 *hh, *hlp, *wqh, *wql, *woh, *wol, *ch, *cl;
    cudaGetSymbolAddress((void**)&hh,  g_hh);
    cudaGetSymbolAddress((void**)&hlp, g_hl);
    cudaGetSymbolAddress((void**)&wqh, g_wqh);
    cudaGetSymbolAddress((void**)&wql, g_wql);
    cudaGetSymbolAddress((void**)&woh, g_woh);
    cudaGetSymbolAddress((void**)&wol, g_wol);
    cudaGetSymbolAddress((void**)&ch,  g_ch);
    cudaGetSymbolAddress((void**)&cl,  g_cl);
    float* qkvp;
    cudaGetSymbolAddress((void**)&qkvp, g_qkv);

    cudaFuncSetAttribute((const void*)gemm_tc<false, true>,
                         cudaFuncAttributeMaxDynamicSharedMemorySize, GEMM_SMEM);
    cudaFuncSetAttribute((const void*)gemm_tc<true, false>,
                         cudaFuncAttributeMaxDynamicSharedMemorySize, GEMM_SMEM);
    cudaFuncSetAttribute(attn_kernel,
                         cudaFuncAttributeMaxDynamicSharedMemorySize, ATTN_SMEM);

    rope_tab_kernel<<<L_, 32>>>();
    convw_kernel<<<(D_ * D3_ / 4 + 255) / 256, 256>>>(wqkv, wqh, wql, D_ * D3_ / 4);
    convw_kernel<<<(D_ * D_ / 4 + 255) / 256, 256>>>(wout, woh, wol, D_ * D_ / 4);
    ln1_kernel<<<R_, 256>>>(x, ln1w, ln1b);
    gemm_tc<false, true><<<dim3(D3_ / 64, R_ / 128), 256, GEMM_SMEM>>>(
        hh, hlp, wqh, wql, qkvp, D3_);
    qkln_rope_kernel<<<dim3(R_, 2), 256>>>(qlnw, klnw);
    attn_kernel<<<dim3(L_ / 128, H_, B_), 256, ATTN_SMEM>>>(seq);
    gemm_tc<true, false><<<dim3(D_ / 64, R_ / 128), 256, GEMM_SMEM>>>(
        ch, cl, woh, wol, out, D_);
}

// round 16
// speedup vs baseline: 1.0925x; 1.0925x over previous
#include <cuda_runtime.h>
#include <cuda_bf16.h>
#include <math.h>
#include <stdint.h>

#define B_  2
#define L_  2048
#define D_  1024
#define H_  16
#define DH_ 64
#define R_  (B_ * L_)
#define D3_ (3 * D_)
#define PERSIST 296   // 148 SMs x 2 blocks

// ---------------- scratch ----------------------------------------------------
__device__ float g_qkv[(size_t)R_ * D3_];
__device__ __nv_bfloat16 g_hh[(size_t)R_ * D_];
__device__ __nv_bfloat16 g_hl[(size_t)R_ * D_];
__device__ __nv_bfloat16 g_qh[(size_t)B_ * H_ * L_ * DH_];
__device__ __nv_bfloat16 g_ql[(size_t)B_ * H_ * L_ * DH_];
__device__ __nv_bfloat16 g_kh[(size_t)B_ * H_ * L_ * DH_];
__device__ __nv_bfloat16 g_kl[(size_t)B_ * H_ * L_ * DH_];
__device__ __nv_bfloat16 g_vh[(size_t)B_ * H_ * L_ * DH_];
__device__ __nv_bfloat16 g_vl[(size_t)B_ * H_ * L_ * DH_];
__device__ __nv_bfloat16 g_ch[(size_t)B_ * H_ * L_ * DH_];
__device__ __nv_bfloat16 g_cl[(size_t)B_ * H_ * L_ * DH_];
__device__ __nv_bfloat16 g_wqh[(size_t)D_ * D3_];
__device__ __nv_bfloat16 g_wql[(size_t)D_ * D3_];
__device__ __nv_bfloat16 g_woh[(size_t)D_ * D_];
__device__ __nv_bfloat16 g_wol[(size_t)D_ * D_];
__device__ float g_cos[L_ * 32];
__device__ float g_sin[L_ * 32];

// ---------------- helpers ----------------------------------------------------
__device__ __forceinline__ uint32_t pk(float a, float b) {
    __nv_bfloat162 t = __floats2bfloat162_rn(a, b);
    return *reinterpret_cast<uint32_t*>(&t);
}
__device__ __forceinline__ void hl(float x, float& h, float& l) {
    h = __bfloat162float(__float2bfloat16(x));
    l = x - h;
}
__device__ __forceinline__ void cvt4(float4 v, uint32_t& h01, uint32_t& h23,
                                     uint32_t& l01, uint32_t& l23) {
    float hx, lx, hy, ly, hz, lz, hw, lw;
    hl(v.x, hx, lx); hl(v.y, hy, ly); hl(v.z, hz, lz); hl(v.w, hw, lw);
    h01 = pk(hx, hy); h23 = pk(hz, hw);
    l01 = pk(lx, ly); l23 = pk(lz, lw);
}
__device__ __forceinline__ void ldsm4(uint32_t a, uint32_t& r0, uint32_t& r1,
                                      uint32_t& r2, uint32_t& r3) {
    asm volatile("ldmatrix.sync.aligned.m8n8.x4.shared.b16 {%0,%1,%2,%3},[%4];"
                 : "=r"(r0), "=r"(r1), "=r"(r2), "=r"(r3) : "r"(a));
}
__device__ __forceinline__ void ldsm4t(uint32_t a, uint32_t& r0, uint32_t& r1,
                                       uint32_t& r2, uint32_t& r3) {
    asm volatile("ldmatrix.sync.aligned.m8n8.x4.trans.shared.b16 {%0,%1,%2,%3},[%4];"
                 : "=r"(r0), "=r"(r1), "=r"(r2), "=r"(r3) : "r"(a));
}
__device__ __forceinline__ void mma16(float* acc, const uint32_t* a,
                                      uint32_t b0, uint32_t b1) {
    asm volatile(
        "mma.sync.aligned.m16n8k16.row.col.f32.bf16.bf16.f32 "
        "{%0,%1,%2,%3},{%4,%5,%6,%7},{%8,%9},{%0,%1,%2,%3};"
        : "+f"(acc[0]), "+f"(acc[1]), "+f"(acc[2]), "+f"(acc[3])
        : "r"(a[0]), "r"(a[1]), "r"(a[2]), "r"(a[3]), "r"(b0), "r"(b1));
}
__device__ __forceinline__ void cpa16(uint32_t dst, const void* src) {
    asm volatile("cp.async.cg.shared.global [%0], [%1], 16;" :: "r"(dst), "l"(src) : "memory");
}
__device__ __forceinline__ void cp_commit() {
    asm volatile("cp.async.commit_group;" ::: "memory");
}
template<int N> __device__ __forceinline__ void cp_wait() {
    asm volatile("cp.async.wait_group %0;" :: "n"(N) : "memory");
}

// ---------------- RoPE table -------------------------------------------------
__global__ void rope_tab_kernel() {
    int l = blockIdx.x;
    int j = threadIdx.x;
    float inv_f = (float)pow(10000.0, -(double)j / 32.0);
    float ang_f = (float)l * inv_f;
    double a = (double)ang_f;
    g_cos[l * 32 + j] = (float)cos(a);
    g_sin[l * 32 + j] = (float)sin(a);
}

// ---------------- weight fp32 -> bf16 hi/lo ----------------------------------
__global__ void __launch_bounds__(256) convw_kernel(const float* __restrict__ w,
                                                    __nv_bfloat16* __restrict__ wh,
                                                    __nv_bfloat16* __restrict__ wl,
                                                    int n4) {
    int i = blockIdx.x * 256 + threadIdx.x;
    if (i >= n4) return;
    float4 v = ((const float4*)w)[i];
    uint32_t h01, h23, l01, l23;
    cvt4(v, h01, h23, l01, l23);
    ((uint2*)wh)[i] = make_uint2(h01, h23);
    ((uint2*)wl)[i] = make_uint2(l01, l23);
}

// ---------------- LN1 ---------------------------------------------------------
__global__ void __launch_bounds__(256) ln1_kernel(const float* __restrict__ x,
                                                  const float* __restrict__ w,
                                                  const float* __restrict__ b) {
    __shared__ float sa[8], sb[8];
    int row = blockIdx.x;
    int t = threadIdx.x;
    float4 v = ((const float4*)(x + (size_t)row * D_))[t];
    float s  = v.x + v.y + v.z + v.w;
    float ss = v.x * v.x + v.y * v.y + v.z * v.z + v.w * v.w;
#pragma unroll
    for (int o = 16; o > 0; o >>= 1) {
        s  += __shfl_xor_sync(0xffffffffu, s, o);
        ss += __shfl_xor_sync(0xffffffffu, ss, o);
    }
    if ((t & 31) == 0) { sa[t >> 5] = s; sb[t >> 5] = ss; }
    __syncthreads();
    float ts = 0.f, tss = 0.f;
#pragma unroll
    for (int i = 0; i < 8; i++) { ts += sa[i]; tss += sb[i]; }
    float mu  = ts * (1.0f / D_);
    float var = tss * (1.0f / D_) - mu * mu;
    float rs  = rsqrtf(var + 1e-5f);
    float4 wv = ((const float4*)w)[t];
    float4 bv = ((const float4*)b)[t];
    float4 o;
    o.x = (v.x - mu) * rs * wv.x + bv.x;
    o.y = (v.y - mu) * rs * wv.y + bv.y;
    o.z = (v.z - mu) * rs * wv.z + bv.z;
    o.w = (v.w - mu) * rs * wv.w + bv.w;
    uint32_t h01, h23, l01, l23;
    cvt4(o, h01, h23, l01, l23);
    ((uint2*)(g_hh + (size_t)row * D_))[t] = make_uint2(h01, h23);
    ((uint2*)(g_hl + (size_t)row * D_))[t] = make_uint2(l01, l23);
}

// ---------------- q/k LN + RoPE -----------------------------------------------
__global__ void __launch_bounds__(256) qkln_rope_kernel(const float* __restrict__ qw,
                                                        const float* __restrict__ kw) {
    __shared__ float sa[8], sb[8];
    __shared__ float sv[D_];
    int row = blockIdx.x;
    int which = blockIdx.y;
    int t = threadIdx.x;
    int bb = row >> 11, l = row & (L_ - 1);

    float* base = g_qkv + (size_t)row * D3_ + which * D_;
    const float* w = which ? kw : qw;

    float4 v = ((const float4*)base)[t];
    float s  = v.x + v.y + v.z + v.w;
    float ss = v.x * v.x + v.y * v.y + v.z * v.z + v.w * v.w;
#pragma unroll
    for (int o = 16; o > 0; o >>= 1) {
        s  += __shfl_xor_sync(0xffffffffu, s, o);
        ss += __shfl_xor_sync(0xffffffffu, ss, o);
    }
    if ((t & 31) == 0) { sa[t >> 5] = s; sb[t >> 5] = ss; }
    __syncthreads();
    float ts = 0.f, tss = 0.f;
#pragma unroll
    for (int i = 0; i < 8; i++) { ts += sa[i]; tss += sb[i]; }
    float mu  = ts * (1.0f / D_);
    float var = tss * (1.0f / D_) - mu * mu;
    float rs  = rsqrtf(var + 1e-5f);
    float4 wv = ((const float4*)w)[t];
    sv[4 * t + 0] = (v.x - mu) * rs * wv.x;
    sv[4 * t + 1] = (v.y - mu) * rs * wv.y;
    sv[4 * t + 2] = (v.z - mu) * rs * wv.z;
    sv[4 * t + 3] = (v.w - mu) * rs * wv.w;
    __syncthreads();

    float res[4];
#pragma unroll
    for (int c = 0; c < 4; c++) {
        int col = 4 * t + c;
        int d = col & 63, dd = d & 31;
        float cs = g_cos[l * 32 + dd];
        float sn = g_sin[l * 32 + dd];
        float y = sv[col];
        res[c] = (d < 32) ? (y * cs - sv[col + 32] * sn)
                          : (y * cs + sv[col - 32] * sn);
    }
    uint32_t h01, h23, l01, l23;
    cvt4(make_float4(res[0], res[1], res[2], res[3]), h01, h23, l01, l23);
    int col = 4 * t, hh = col >> 6, d = col & 63;
    size_t di = (((size_t)(bb * H_ + hh)) * L_ + l) * 64 + d;
    __nv_bfloat16* oh = which ? g_kh : g_qh;
    __nv_bfloat16* ol = which ? g_kl : g_ql;
    *(uint2*)(oh + di) = make_uint2(h01, h23);
    *(uint2*)(ol + di) = make_uint2(l01, l23);
}

// ---------------- bf16x2 GEMM: persistent, 128x64 tile, BK=64, 96KB ----------
#define GS_SZ   49152
#define GS_BH   32768
#define GS_BL   40960
#define GEMM_SMEM (2 * GS_SZ)

template<bool HEADMAJ>
__device__ __forceinline__ void g_prefetch(uint32_t base, int c, int tid,
        int m0, int n0, int N,
        const __nv_bfloat16* __restrict__ Ahg, const __nv_bfloat16* __restrict__ Alg,
        const __nv_bfloat16* __restrict__ Bhg, const __nv_bfloat16* __restrict__ Blg) {
    uint32_t sb = base + (c & 1) * GS_SZ;
#pragma unroll
    for (int i = 0; i < 4; i++) {        // A: 128 rows x 8 segs
        int id = tid + i * 256;
        int row = id >> 3, sg = id & 7;
        size_t asrc;
        if (HEADMAJ) {
            int gr = m0 + row;
            int bb = gr >> 11, l = gr & (L_ - 1);
            asrc = (((size_t)(bb * H_ + c)) * L_ + l) * 64 + sg * 8;
        } else {
            asrc = (size_t)(m0 + row) * 1024 + c * 64 + sg * 8;
        }
        uint32_t ad = sb + row * 128 + ((sg * 16) ^ ((row & 7) << 4));
        cpa16(ad,         Ahg + asrc);
        cpa16(ad + 16384, Alg + asrc);
    }
#pragma unroll
    for (int i = 0; i < 2; i++) {        // B: 64 k-rows x 8 segs (128B rows)
        int id = tid + i * 256;
        int k = id >> 3, sg = id & 7;
        size_t bsrc = (size_t)(c * 64 + k) * N + n0 + sg * 8;
        uint32_t bd = sb + GS_BH + k * 128 + ((sg * 16) ^ ((k & 7) << 4));
        cpa16(bd,        Bhg + bsrc);
        cpa16(bd + 8192, Blg + bsrc);
    }
    cp_commit();
}

template<bool HEADMAJ, bool VOUT>
__global__ void __launch_bounds__(256) gemm_tc(
        const __nv_bfloat16* __restrict__ Ahg, const __nv_bfloat16* __restrict__ Alg,
        const __nv_bfloat16* __restrict__ Bhg, const __nv_bfloat16* __restrict__ Blg,
        float* __restrict__ C, int N, int ntiles) {
    extern __shared__ __align__(16) char sm[];
    uint32_t base = (uint32_t)__cvta_generic_to_shared(sm);
    int tid = threadIdx.x, wid = tid >> 5, lane = tid & 31;
    int wm = wid >> 1, wn = wid & 1;
    int nx = N >> 6;

    for (int idx = blockIdx.x; idx < ntiles; idx += PERSIST) {
        int m0 = (idx / nx) * 128, n0 = (idx % nx) * 64;

        g_prefetch<HEADMAJ>(base, 0, tid, m0, n0, N, Ahg, Alg, Bhg, Blg);

        float acc[2][4][4] = {};
        for (int c = 0; c < 16; c++) {
            if (c + 1 < 16) {
                g_prefetch<HEADMAJ>(base, c + 1, tid, m0, n0, N, Ahg, Alg, Bhg, Blg);
                cp_wait<1>();
            } else {
                cp_wait<0>();
            }
            __syncthreads();
            uint32_t sb = base + (c & 1) * GS_SZ;
#pragma unroll
            for (int ks = 0; ks < 4; ks++) {
                uint32_t ah[2][4], al[2][4];
#pragma unroll
                for (int mt = 0; mt < 2; mt++) {
                    int row = wm * 32 + mt * 16 + (lane & 15);
                    uint32_t ad = sb + row * 128 +
                                  ((ks * 32 + (lane >> 4) * 16) ^ ((row & 7) << 4));
                    ldsm4(ad,         ah[mt][0], ah[mt][1], ah[mt][2], ah[mt][3]);
                    ldsm4(ad + 16384, al[mt][0], al[mt][1], al[mt][2], al[mt][3]);
                }
#pragma unroll
                for (int np = 0; np < 2; np++) {
                    int k = ks * 16 + (lane & 15);
                    int ntile = wn * 4 + np * 2 + (lane >> 4);
                    uint32_t bd = sb + GS_BH + k * 128 +
                                  ((ntile * 16) ^ ((k & 7) << 4));
                    uint32_t bh0, bh1, bh2, bh3, bl0, bl1, bl2, bl3;
                    ldsm4t(bd,        bh0, bh1, bh2, bh3);
                    ldsm4t(bd + 8192, bl0, bl1, bl2, bl3);
#pragma unroll
                    for (int mt = 0; mt < 2; mt++) {
                        mma16(acc[mt][np * 2],     ah[mt], bh0, bh1);
                        mma16(acc[mt][np * 2],     al[mt], bh0, bh1);
                        mma16(acc[mt][np * 2],     ah[mt], bl0, bl1);
                        mma16(acc[mt][np * 2 + 1], ah[mt], bh2, bh3);
                        mma16(acc[mt][np * 2 + 1], al[mt], bh2, bh3);
                        mma16(acc[mt][np * 2 + 1], ah[mt], bl2, bl3);
                    }
                }
            }
            __syncthreads();
        }
        // epilogue
        if (VOUT && n0 >= 2048) {
#pragma unroll
            for (int mt = 0; mt < 2; mt++) {
                int r = m0 + wm * 32 + mt * 16 + (lane >> 2);
                int ccv = (n0 - 2048) + wn * 32 + (lane & 3) * 2;
                int bb = r >> 11, lv = r & (L_ - 1);
#pragma unroll
                for (int nt = 0; nt < 4; nt++) {
                    int col = ccv + nt * 8;
                    int hh = col >> 6, d = col & 63;
                    size_t di = (((size_t)(bb * H_ + hh)) * L_ + lv) * 64 + d;
                    float h0, l0, h1, l1, h2, l2, h3, l3;
                    hl(acc[mt][nt][0], h0, l0); hl(acc[mt][nt][1], h1, l1);
                    hl(acc[mt][nt][2], h2, l2); hl(acc[mt][nt][3], h3, l3);
                    *(uint32_t*)(g_vh + di) = pk(h0, h1);
                    *(uint32_t*)(g_vl + di) = pk(l0, l1);
                    *(uint32_t*)(g_vh + di + (size_t)8 * 64) = pk(h2, h3);
                    *(uint32_t*)(g_vl + di + (size_t)8 * 64) = pk(l2, l3);
                }
            }
        } else {
#pragma unroll
            for (int mt = 0; mt < 2; mt++) {
                int r = m0 + wm * 32 + mt * 16 + (lane >> 2);
                int cc = n0 + wn * 32 + (lane & 3) * 2;
#pragma unroll
                for (int nt = 0; nt < 4; nt++) {
                    *(float2*)(C + (size_t)r * N + cc + nt * 8) =
                        make_float2(acc[mt][nt][0], acc[mt][nt][1]);
                    *(float2*)(C + (size_t)(r + 8) * N + cc + nt * 8) =
                        make_float2(acc[mt][nt][2], acc[mt][nt][3]);
                }
            }
        }
        __syncthreads();   // epilogue smem reads done before next tile prefetch
    }
}

// ---------------- flash attention: R9/R12 exact -------------------------------
#define ATTN_SMEM 98560

__global__ void __launch_bounds__(256) attn_kernel(const int* __restrict__ seq_id) {
    extern __shared__ __align__(16) char smA[];
    char* Ps = smA + 65536;
    int* kseq = (int*)(smA + 98304);
    uint32_t base = (uint32_t)__cvta_generic_to_shared(smA);
    uint32_t qB = base, kB = base + 32768, vB = base + 49152, pB = base + 65536;

    int qt = blockIdx.x, h = blockIdx.y, b = blockIdx.z;
    int tid = threadIdx.x, wid = tid >> 5, lane = tid & 31;
    int q0 = qt * 128;
    size_t bh = (size_t)(b * H_ + h);
    const int* seqb = seq_id + b * L_;

#pragma unroll
    for (int i = 0; i < 4; i++) {
        int id = tid + i * 256;
        int q = id >> 3, sg = id & 7;
        size_t src = (bh * L_ + q0 + q) * 64 + sg * 8;
        uint32_t ad = qB + q * 128 + ((sg * 16) ^ ((q & 7) << 4));
        cpa16(ad,         g_qh + src);
        cpa16(ad + 16384, g_ql + src);
    }
    cp_commit();

    int qs0 = seqb[q0 + wid * 16 + (lane >> 2)];
    int qs1 = seqb[q0 + wid * 16 + (lane >> 2) + 8];

    int sa = seqb[q0], sb2 = seqb[q0 + 127];
    int lo = 0, hi = L_;
    while (lo < hi) { int mid = (lo + hi) >> 1; if (seqb[mid] < sa) lo = mid + 1; else hi = mid; }
    int klo = lo;
    lo = 0; hi = L_;
    while (lo < hi) { int mid = (lo + hi) >> 1; if (seqb[mid] <= sb2) lo = mid + 1; else hi = mid; }
    int khi = lo;
    int kt0 = klo >> 6, kt1 = (khi - 1) >> 6;

    float O[8][4] = {};
    float m0v = -1e30f, m1v = -1e30f, l0s = 0.f, l1s = 0.f;
    int c0 = (lane & 3) * 2;

    for (int kt = kt0; kt <= kt1; kt++) {
        __syncthreads();
#pragma unroll
        for (int i = 0; i < 2; i++) {
            int id = tid + i * 256;
            int kp = id >> 3, sg = id & 7;
            size_t src = (bh * L_ + kt * 64 + kp) * 64 + sg * 8;
            uint32_t sw = (sg * 16) ^ ((kp & 7) << 4);
            cpa16(kB + kp * 128 + sw,        g_kh + src);
            cpa16(kB + kp * 128 + sw + 8192, g_kl + src);
            cpa16(vB + kp * 128 + sw,        g_vh + src);
            cpa16(vB + kp * 128 + sw + 8192, g_vl + src);
        }
        cp_commit();
        if (tid < 64) kseq[tid] = seqb[kt * 64 + tid];
        cp_wait<0>();
        __syncthreads();

        // S = Q K^T (3-term)
        float S[8][4] = {};
#pragma unroll
        for (int ds = 0; ds < 4; ds++) {
            uint32_t ah[4], al[4];
            int row = wid * 16 + (lane & 15);
            uint32_t ad = qB + row * 128 +
                          ((ds * 32 + (lane >> 4) * 16) ^ ((row & 7) << 4));
            ldsm4(ad,         ah[0], ah[1], ah[2], ah[3]);
            ldsm4(ad + 16384, al[0], al[1], al[2], al[3]);
#pragma unroll
            for (int np = 0; np < 4; np++) {
                int kpos = (np * 2 + (lane >> 4)) * 8 + (lane & 7);
                int dbyte = ds * 32 + ((lane >> 3) & 1) * 16;
                uint32_t kd = kB + kpos * 128 + (dbyte ^ ((kpos & 7) << 4));
                uint32_t bh0, bh1, bh2, bh3, bl0, bl1, bl2, bl3;
                ldsm4(kd,        bh0, bh1, bh2, bh3);
                ldsm4(kd + 8192, bl0, bl1, bl2, bl3);
                mma16(S[np * 2],     ah, bh0, bh1);
                mma16(S[np * 2],     al, bh0, bh1);
                mma16(S[np * 2],     ah, bl0, bl1);
                mma16(S[np * 2 + 1], ah, bh2, bh3);
                mma16(S[np * 2 + 1], al, bh2, bh3);
                mma16(S[np * 2 + 1], ah, bl2, bl3);
            }
        }
        // mask + scale + online softmax
        float mx0 = -1e30f, mx1 = -1e30f;
#pragma unroll
        for (int nt = 0; nt < 8; nt++) {
            int k0 = kseq[nt * 8 + c0], k1 = kseq[nt * 8 + c0 + 1];
            S[nt][0] = (qs0 == k0) ? S[nt][0] * 0.125f : -1e30f;
            S[nt][1] = (qs0 == k1) ? S[nt][1] * 0.125f : -1e30f;
            S[nt][2] = (qs1 == k0) ? S[nt][2] * 0.125f : -1e30f;
            S[nt][3] = (qs1 == k1) ? S[nt][3] * 0.125f : -1e30f;
            mx0 = fmaxf(mx0, fmaxf(S[nt][0], S[nt][1]));
            mx1 = fmaxf(mx1, fmaxf(S[nt][2], S[nt][3]));
        }
        mx0 = fmaxf(mx0, __shfl_xor_sync(0xffffffffu, mx0, 1));
        mx0 = fmaxf(mx0, __shfl_xor_sync(0xffffffffu, mx0, 2));
        mx1 = fmaxf(mx1, __shfl_xor_sync(0xffffffffu, mx1, 1));
        mx1 = fmaxf(mx1, __shfl_xor_sync(0xffffffffu, mx1, 2));
        float mn0 = fmaxf(m0v, mx0), mn1 = fmaxf(m1v, mx1);
        float al0 = __expf(m0v - mn0), al1 = __expf(m1v - mn1);
        m0v = mn0; m1v = mn1;

        int r = wid * 16 + (lane >> 2);
        int r2 = r + 8;
        float rs0 = 0.f, rs1 = 0.f;
#pragma unroll
        for (int nt = 0; nt < 8; nt++) {
            float p00 = (S[nt][0] <= -9e29f) ? 0.f : __expf(S[nt][0] - mn0);
            float p01 = (S[nt][1] <= -9e29f) ? 0.f : __expf(S[nt][1] - mn0);
            float p10 = (S[nt][2] <= -9e29f) ? 0.f : __expf(S[nt][2] - mn1);
            float p11 = (S[nt][3] <= -9e29f) ? 0.f : __expf(S[nt][3] - mn1);
            rs0 += p00 + p01;
            rs1 += p10 + p11;
            int c = nt * 8 + c0;
            float h00, lo00, h01v, lo01, h10, lo10, h11v, lo11;
            hl(p00, h00, lo00); hl(p01, h01v, lo01);
            hl(p10, h10, lo10); hl(p11, h11v, lo11);
            int sw0 = (c * 2) ^ ((r & 7) << 4);
            char* pp = Ps + r * 256;
            *(uint32_t*)(pp + sw0)       = pk(h00, h01v);
            *(uint32_t*)(pp + 128 + sw0) = pk(lo00, lo01);
            int sw2 = (c * 2) ^ ((r2 & 7) << 4);
            char* pp2 = Ps + r2 * 256;
            *(uint32_t*)(pp2 + sw2)       = pk(h10, h11v);
            *(uint32_t*)(pp2 + 128 + sw2) = pk(lo10, lo11);
        }
        rs0 += __shfl_xor_sync(0xffffffffu, rs0, 1);
        rs0 += __shfl_xor_sync(0xffffffffu, rs0, 2);
        rs1 += __shfl_xor_sync(0xffffffffu, rs1, 1);
        rs1 += __shfl_xor_sync(0xffffffffu, rs1, 2);
        l0s = l0s * al0 + rs0;
        l1s = l1s * al1 + rs1;
#pragma unroll
        for (int nt = 0; nt < 8; nt++) {
            O[nt][0] *= al0; O[nt][1] *= al0;
            O[nt][2] *= al1; O[nt][3] *= al1;
        }
        __syncwarp();

        // O += P V (3-term)
#pragma unroll
        for (int ks = 0; ks < 4; ks++) {
            uint32_t ah[4], al[4];
            int row = wid * 16 + (lane & 15);
            uint32_t ad = pB + row * 256 +
                          ((ks * 32 + (lane >> 4) * 16) ^ ((row & 7) << 4));
            ldsm4(ad,       ah[0], ah[1], ah[2], ah[3]);
            ldsm4(ad + 128, al[0], al[1], al[2], al[3]);
#pragma unroll
            for (int np = 0; np < 4; np++) {
                int kpos = ks * 16 + ((lane >> 3) & 1) * 8 + (lane & 7);
                int dtile = np * 2 + (lane >> 4);
                uint32_t vd = vB + kpos * 128 + ((dtile * 16) ^ ((kpos & 7) << 4));
                uint32_t bh0, bh1, bh2, bh3, bl0, bl1, bl2, bl3;
                ldsm4t(vd,        bh0, bh1, bh2, bh3);
                ldsm4t(vd + 8192, bl0, bl1, bl2, bl3);
                mma16(O[np * 2],     ah, bh0, bh1);
                mma16(O[np * 2],     al, bh0, bh1);
                mma16(O[np * 2],     ah, bl0, bl1);
                mma16(O[np * 2 + 1], ah, bh2, bh3);
                mma16(O[np * 2 + 1], al, bh2, bh3);
                mma16(O[np * 2 + 1], ah, bl2, bl3);
            }
        }
    }
    // epilogue
    float inv0 = 1.0f / l0s, inv1 = 1.0f / l1s;
    int r0 = q0 + wid * 16 + (lane >> 2);
    size_t ob = (bh * L_ + r0) * 64 + (lane & 3) * 2;
#pragma unroll
    for (int nt = 0; nt < 8; nt++) {
        float v0 = O[nt][0] * inv0, v1 = O[nt][1] * inv0;
        float v2 = O[nt][2] * inv1, v3 = O[nt][3] * inv1;
        float h0, lo0, h1, lo1, h2, lo2, h3, lo3;
        hl(v0, h0, lo0); hl(v1, h1, lo1); hl(v2, h2, lo2); hl(v3, h3, lo3);
        *(uint32_t*)(g_ch + ob + nt * 8) = pk(h0, h1);
        *(uint32_t*)(g_cl + ob + nt * 8) = pk(lo0, lo1);
        *(uint32_t*)(g_ch + ob + (size_t)8 * 64 + nt * 8) = pk(h2, h3);
        *(uint32_t*)(g_cl + ob + (size_t)8 * 64 + nt * 8) = pk(lo2, lo3);
    }
}

// ---------------- launch ------------------------------------------------------
extern "C" void kernel_launch(void* const* d_in, const int* in_sizes, int n_in,
                              void* d_out, int out_size) {
    const float* x    = (const float*)d_in[0];
    const int*   seq  = (const int*)d_in[1];
    const float* ln1w = (const float*)d_in[2];
    const float* ln1b = (const float*)d_in[3];
    const float* wqkv = (const float*)d_in[4];
    const float* qlnw = (const float*)d_in[5];
    const float* klnw = (const float*)d_in[6];
    const float* wout = (const float*)d_in[7];
    float* out = (float*)d_out;

    __nv_bfloat16 *hh, *hlp, *wqh, *wql, *woh, *wol, *ch, *cl;
    cudaGetSymbolAddress((void**)&hh,  g_hh);
    cudaGetSymbolAddress((void**)&hlp, g_hl);
    cudaGetSymbolAddress((void**)&wqh, g_wqh);
    cudaGetSymbolAddress((void**)&wql, g_wql);
    cudaGetSymbolAddress((void**)&woh, g_woh);
    cudaGetSymbolAddress((void**)&wol, g_wol);
    cudaGetSymbolAddress((void**)&ch,  g_ch);
    cudaGetSymbolAddress((void**)&cl,  g_cl);
    float* qkvp;
    cudaGetSymbolAddress((void**)&qkvp, g_qkv);

    cudaFuncSetAttribute((const void*)gemm_tc<false, true>,
                         cudaFuncAttributeMaxDynamicSharedMemorySize, GEMM_SMEM);
    cudaFuncSetAttribute((const void*)gemm_tc<true, false>,
                         cudaFuncAttributeMaxDynamicSharedMemorySize, GEMM_SMEM);
    cudaFuncSetAttribute(attn_kernel,
                         cudaFuncAttributeMaxDynamicSharedMemorySize, ATTN_SMEM);

    rope_tab_kernel<<<L_, 32>>>();
    convw_kernel<<<(D_ * D3_ / 4 + 255) / 256, 256>>>(wqkv, wqh, wql, D_ * D3_ / 4);
    convw_kernel<<<(D_ * D_ / 4 + 255) / 256, 256>>>(wout, woh, wol, D_ * D_ / 4);
    ln1_kernel<<<R_, 256>>>(x, ln1w, ln1b);
    gemm_tc<false, true><<<PERSIST, 256, GEMM_SMEM>>>(
        hh, hlp, wqh, wql, qkvp, D3_, (R_ / 128) * (D3_ / 64));
    qkln_rope_kernel<<<dim3(R_, 2), 256>>>(qlnw, klnw);
    attn_kernel<<<dim3(L_ / 128, H_, B_), 256, ATTN_SMEM>>>(seq);
    gemm_tc<true, false><<<PERSIST, 256, GEMM_SMEM>>>(
        ch, cl, woh, wol, out, D_, (R_ / 128) * (D_ / 64));
}

// round 17
// speedup vs baseline: 1.1423x; 1.0456x over previous
#include <cuda_runtime.h>
#include <cuda_bf16.h>
#include <math.h>
#include <stdint.h>

#define B_  2
#define L_  2048
#define D_  1024
#define H_  16
#define DH_ 64
#define R_  (B_ * L_)
#define D3_ (3 * D_)

// ---------------- scratch ----------------------------------------------------
__device__ float g_qkv[(size_t)R_ * D3_];
__device__ __nv_bfloat16 g_hh[(size_t)R_ * D_];
__device__ __nv_bfloat16 g_hl[(size_t)R_ * D_];
__device__ __nv_bfloat16 g_qh[(size_t)B_ * H_ * L_ * DH_];
__device__ __nv_bfloat16 g_ql[(size_t)B_ * H_ * L_ * DH_];
__device__ __nv_bfloat16 g_kh[(size_t)B_ * H_ * L_ * DH_];
__device__ __nv_bfloat16 g_kl[(size_t)B_ * H_ * L_ * DH_];
__device__ __nv_bfloat16 g_vh[(size_t)B_ * H_ * L_ * DH_];
__device__ __nv_bfloat16 g_vl[(size_t)B_ * H_ * L_ * DH_];
__device__ __nv_bfloat16 g_ch[(size_t)B_ * H_ * L_ * DH_];
__device__ __nv_bfloat16 g_cl[(size_t)B_ * H_ * L_ * DH_];
__device__ __nv_bfloat16 g_wqh[(size_t)D_ * D3_];
__device__ __nv_bfloat16 g_wql[(size_t)D_ * D3_];
__device__ __nv_bfloat16 g_woh[(size_t)D_ * D_];
__device__ __nv_bfloat16 g_wol[(size_t)D_ * D_];
__device__ float g_cos[L_ * 32];
__device__ float g_sin[L_ * 32];

// ---------------- helpers ----------------------------------------------------
__device__ __forceinline__ uint32_t pk(float a, float b) {
    __nv_bfloat162 t = __floats2bfloat162_rn(a, b);
    return *reinterpret_cast<uint32_t*>(&t);
}
__device__ __forceinline__ void hl(float x, float& h, float& l) {
    h = __bfloat162float(__float2bfloat16(x));
    l = x - h;
}
__device__ __forceinline__ void cvt4(float4 v, uint32_t& h01, uint32_t& h23,
                                     uint32_t& l01, uint32_t& l23) {
    float hx, lx, hy, ly, hz, lz, hw, lw;
    hl(v.x, hx, lx); hl(v.y, hy, ly); hl(v.z, hz, lz); hl(v.w, hw, lw);
    h01 = pk(hx, hy); h23 = pk(hz, hw);
    l01 = pk(lx, ly); l23 = pk(lz, lw);
}
__device__ __forceinline__ void ldsm4(uint32_t a, uint32_t& r0, uint32_t& r1,
                                      uint32_t& r2, uint32_t& r3) {
    asm volatile("ldmatrix.sync.aligned.m8n8.x4.shared.b16 {%0,%1,%2,%3},[%4];"
                 : "=r"(r0), "=r"(r1), "=r"(r2), "=r"(r3) : "r"(a));
}
__device__ __forceinline__ void ldsm4t(uint32_t a, uint32_t& r0, uint32_t& r1,
                                       uint32_t& r2, uint32_t& r3) {
    asm volatile("ldmatrix.sync.aligned.m8n8.x4.trans.shared.b16 {%0,%1,%2,%3},[%4];"
                 : "=r"(r0), "=r"(r1), "=r"(r2), "=r"(r3) : "r"(a));
}
__device__ __forceinline__ void mma16(float* acc, const uint32_t* a,
                                      uint32_t b0, uint32_t b1) {
    asm volatile(
        "mma.sync.aligned.m16n8k16.row.col.f32.bf16.bf16.f32 "
        "{%0,%1,%2,%3},{%4,%5,%6,%7},{%8,%9},{%0,%1,%2,%3};"
        : "+f"(acc[0]), "+f"(acc[1]), "+f"(acc[2]), "+f"(acc[3])
        : "r"(a[0]), "r"(a[1]), "r"(a[2]), "r"(a[3]), "r"(b0), "r"(b1));
}
__device__ __forceinline__ void cpa16(uint32_t dst, const void* src) {
    asm volatile("cp.async.cg.shared.global [%0], [%1], 16;" :: "r"(dst), "l"(src) : "memory");
}
__device__ __forceinline__ void cp_commit() {
    asm volatile("cp.async.commit_group;" ::: "memory");
}
template<int N> __device__ __forceinline__ void cp_wait() {
    asm volatile("cp.async.wait_group %0;" :: "n"(N) : "memory");
}

// ---------------- RoPE table -------------------------------------------------
__global__ void rope_tab_kernel() {
    int l = blockIdx.x;
    int j = threadIdx.x;
    float inv_f = (float)pow(10000.0, -(double)j / 32.0);
    float ang_f = (float)l * inv_f;
    double a = (double)ang_f;
    g_cos[l * 32 + j] = (float)cos(a);
    g_sin[l * 32 + j] = (float)sin(a);
}

// ---------------- weight fp32 -> bf16 hi/lo ----------------------------------
__global__ void __launch_bounds__(256) convw_kernel(const float* __restrict__ w,
                                                    __nv_bfloat16* __restrict__ wh,
                                                    __nv_bfloat16* __restrict__ wl,
                                                    int n4) {
    int i = blockIdx.x * 256 + threadIdx.x;
    if (i >= n4) return;
    float4 v = ((const float4*)w)[i];
    uint32_t h01, h23, l01, l23;
    cvt4(v, h01, h23, l01, l23);
    ((uint2*)wh)[i] = make_uint2(h01, h23);
    ((uint2*)wl)[i] = make_uint2(l01, l23);
}

// ---------------- LN1 ---------------------------------------------------------
__global__ void __launch_bounds__(256) ln1_kernel(const float* __restrict__ x,
                                                  const float* __restrict__ w,
                                                  const float* __restrict__ b) {
    __shared__ float sa[8], sb[8];
    int row = blockIdx.x;
    int t = threadIdx.x;
    float4 v = ((const float4*)(x + (size_t)row * D_))[t];
    float s  = v.x + v.y + v.z + v.w;
    float ss = v.x * v.x + v.y * v.y + v.z * v.z + v.w * v.w;
#pragma unroll
    for (int o = 16; o > 0; o >>= 1) {
        s  += __shfl_xor_sync(0xffffffffu, s, o);
        ss += __shfl_xor_sync(0xffffffffu, ss, o);
    }
    if ((t & 31) == 0) { sa[t >> 5] = s; sb[t >> 5] = ss; }
    __syncthreads();
    float ts = 0.f, tss = 0.f;
#pragma unroll
    for (int i = 0; i < 8; i++) { ts += sa[i]; tss += sb[i]; }
    float mu  = ts * (1.0f / D_);
    float var = tss * (1.0f / D_) - mu * mu;
    float rs  = rsqrtf(var + 1e-5f);
    float4 wv = ((const float4*)w)[t];
    float4 bv = ((const float4*)b)[t];
    float4 o;
    o.x = (v.x - mu) * rs * wv.x + bv.x;
    o.y = (v.y - mu) * rs * wv.y + bv.y;
    o.z = (v.z - mu) * rs * wv.z + bv.z;
    o.w = (v.w - mu) * rs * wv.w + bv.w;
    uint32_t h01, h23, l01, l23;
    cvt4(o, h01, h23, l01, l23);
    ((uint2*)(g_hh + (size_t)row * D_))[t] = make_uint2(h01, h23);
    ((uint2*)(g_hl + (size_t)row * D_))[t] = make_uint2(l01, l23);
}

// ---------------- q/k LN + RoPE -----------------------------------------------
__global__ void __launch_bounds__(256) qkln_rope_kernel(const float* __restrict__ qw,
                                                        const float* __restrict__ kw) {
    __shared__ float sa[8], sb[8];
    __shared__ float sv[D_];
    int row = blockIdx.x;
    int which = blockIdx.y;
    int t = threadIdx.x;
    int bb = row >> 11, l = row & (L_ - 1);

    float* base = g_qkv + (size_t)row * D3_ + which * D_;
    const float* w = which ? kw : qw;

    float4 v = ((const float4*)base)[t];
    float s  = v.x + v.y + v.z + v.w;
    float ss = v.x * v.x + v.y * v.y + v.z * v.z + v.w * v.w;
#pragma unroll
    for (int o = 16; o > 0; o >>= 1) {
        s  += __shfl_xor_sync(0xffffffffu, s, o);
        ss += __shfl_xor_sync(0xffffffffu, ss, o);
    }
    if ((t & 31) == 0) { sa[t >> 5] = s; sb[t >> 5] = ss; }
    __syncthreads();
    float ts = 0.f, tss = 0.f;
#pragma unroll
    for (int i = 0; i < 8; i++) { ts += sa[i]; tss += sb[i]; }
    float mu  = ts * (1.0f / D_);
    float var = tss * (1.0f / D_) - mu * mu;
    float rs  = rsqrtf(var + 1e-5f);
    float4 wv = ((const float4*)w)[t];
    sv[4 * t + 0] = (v.x - mu) * rs * wv.x;
    sv[4 * t + 1] = (v.y - mu) * rs * wv.y;
    sv[4 * t + 2] = (v.z - mu) * rs * wv.z;
    sv[4 * t + 3] = (v.w - mu) * rs * wv.w;
    __syncthreads();

    float res[4];
#pragma unroll
    for (int c = 0; c < 4; c++) {
        int col = 4 * t + c;
        int d = col & 63, dd = d & 31;
        float cs = g_cos[l * 32 + dd];
        float sn = g_sin[l * 32 + dd];
        float y = sv[col];
        res[c] = (d < 32) ? (y * cs - sv[col + 32] * sn)
                          : (y * cs + sv[col - 32] * sn);
    }
    uint32_t h01, h23, l01, l23;
    cvt4(make_float4(res[0], res[1], res[2], res[3]), h01, h23, l01, l23);
    int col = 4 * t, hh = col >> 6, d = col & 63;
    size_t di = (((size_t)(bb * H_ + hh)) * L_ + l) * 64 + d;
    __nv_bfloat16* oh = which ? g_kh : g_qh;
    __nv_bfloat16* ol = which ? g_kl : g_ql;
    *(uint2*)(oh + di) = make_uint2(h01, h23);
    *(uint2*)(ol + di) = make_uint2(l01, l23);
}

// ---------------- bf16x2 GEMM: 128x64 tile, BK=64, 2 stages, 96KB ------------
#define GS_SZ   49152
#define GS_BH   32768
#define GS_BL   40960
#define GEMM_SMEM (2 * GS_SZ)

template<bool HEADMAJ>
__device__ __forceinline__ void g_prefetch(uint32_t base, int c, int tid,
        int m0, int n0, int N,
        const __nv_bfloat16* __restrict__ Ahg, const __nv_bfloat16* __restrict__ Alg,
        const __nv_bfloat16* __restrict__ Bhg, const __nv_bfloat16* __restrict__ Blg) {
    uint32_t sb = base + (c & 1) * GS_SZ;
#pragma unroll
    for (int i = 0; i < 4; i++) {        // A: 128 rows x 8 segs
        int id = tid + i * 256;
        int row = id >> 3, sg = id & 7;
        size_t asrc;
        if (HEADMAJ) {
            int gr = m0 + row;
            int bb = gr >> 11, l = gr & (L_ - 1);
            asrc = (((size_t)(bb * H_ + c)) * L_ + l) * 64 + sg * 8;
        } else {
            asrc = (size_t)(m0 + row) * 1024 + c * 64 + sg * 8;
        }
        uint32_t ad = sb + row * 128 + ((sg * 16) ^ ((row & 7) << 4));
        cpa16(ad,         Ahg + asrc);
        cpa16(ad + 16384, Alg + asrc);
    }
#pragma unroll
    for (int i = 0; i < 2; i++) {        // B: 64 k-rows x 8 segs (128B rows)
        int id = tid + i * 256;
        int k = id >> 3, sg = id & 7;
        size_t bsrc = (size_t)(c * 64 + k) * N + n0 + sg * 8;
        uint32_t bd = sb + GS_BH + k * 128 + ((sg * 16) ^ ((k & 7) << 4));
        cpa16(bd,        Bhg + bsrc);
        cpa16(bd + 8192, Blg + bsrc);
    }
    cp_commit();
}

template<bool HEADMAJ, bool VOUT>
__global__ void __launch_bounds__(256) gemm_tc(
        const __nv_bfloat16* __restrict__ Ahg, const __nv_bfloat16* __restrict__ Alg,
        const __nv_bfloat16* __restrict__ Bhg, const __nv_bfloat16* __restrict__ Blg,
        float* __restrict__ C, int N) {
    extern __shared__ __align__(16) char sm[];
    uint32_t base = (uint32_t)__cvta_generic_to_shared(sm);
    int tid = threadIdx.x, wid = tid >> 5, lane = tid & 31;
    int wm = wid >> 1, wn = wid & 1;
    int m0 = blockIdx.y * 128, n0 = blockIdx.x * 64;

    g_prefetch<HEADMAJ>(base, 0, tid, m0, n0, N, Ahg, Alg, Bhg, Blg);

    float acc[2][4][4] = {};
    for (int c = 0; c < 16; c++) {
        if (c + 1 < 16) {
            g_prefetch<HEADMAJ>(base, c + 1, tid, m0, n0, N, Ahg, Alg, Bhg, Blg);
            cp_wait<1>();
        } else {
            cp_wait<0>();
        }
        __syncthreads();
        uint32_t sb = base + (c & 1) * GS_SZ;
#pragma unroll
        for (int ks = 0; ks < 4; ks++) {
            uint32_t ah[2][4], al[2][4];
#pragma unroll
            for (int mt = 0; mt < 2; mt++) {
                int row = wm * 32 + mt * 16 + (lane & 15);
                uint32_t ad = sb + row * 128 +
                              ((ks * 32 + (lane >> 4) * 16) ^ ((row & 7) << 4));
                ldsm4(ad,         ah[mt][0], ah[mt][1], ah[mt][2], ah[mt][3]);
                ldsm4(ad + 16384, al[mt][0], al[mt][1], al[mt][2], al[mt][3]);
            }
#pragma unroll
            for (int np = 0; np < 2; np++) {
                int k = ks * 16 + (lane & 15);
                int ntile = wn * 4 + np * 2 + (lane >> 4);
                uint32_t bd = sb + GS_BH + k * 128 +
                              ((ntile * 16) ^ ((k & 7) << 4));
                uint32_t bh0, bh1, bh2, bh3, bl0, bl1, bl2, bl3;
                ldsm4t(bd,        bh0, bh1, bh2, bh3);
                ldsm4t(bd + 8192, bl0, bl1, bl2, bl3);
#pragma unroll
                for (int mt = 0; mt < 2; mt++) {
                    mma16(acc[mt][np * 2],     ah[mt], bh0, bh1);
                    mma16(acc[mt][np * 2],     al[mt], bh0, bh1);
                    mma16(acc[mt][np * 2],     ah[mt], bl0, bl1);
                    mma16(acc[mt][np * 2 + 1], ah[mt], bh2, bh3);
                    mma16(acc[mt][np * 2 + 1], al[mt], bh2, bh3);
                    mma16(acc[mt][np * 2 + 1], ah[mt], bl2, bl3);
                }
            }
        }
        __syncthreads();
    }
    // epilogue
    if (VOUT && n0 >= 2048) {
#pragma unroll
        for (int mt = 0; mt < 2; mt++) {
            int r = m0 + wm * 32 + mt * 16 + (lane >> 2);
            int ccv = (n0 - 2048) + wn * 32 + (lane & 3) * 2;
            int bb = r >> 11, lv = r & (L_ - 1);
#pragma unroll
            for (int nt = 0; nt < 4; nt++) {
                int col = ccv + nt * 8;
                int hh = col >> 6, d = col & 63;
                size_t di = (((size_t)(bb * H_ + hh)) * L_ + lv) * 64 + d;
                float h0, l0, h1, l1, h2, l2, h3, l3;
                hl(acc[mt][nt][0], h0, l0); hl(acc[mt][nt][1], h1, l1);
                hl(acc[mt][nt][2], h2, l2); hl(acc[mt][nt][3], h3, l3);
                *(uint32_t*)(g_vh + di) = pk(h0, h1);
                *(uint32_t*)(g_vl + di) = pk(l0, l1);
                *(uint32_t*)(g_vh + di + (size_t)8 * 64) = pk(h2, h3);
                *(uint32_t*)(g_vl + di + (size_t)8 * 64) = pk(l2, l3);
            }
        }
    } else {
#pragma unroll
        for (int mt = 0; mt < 2; mt++) {
            int r = m0 + wm * 32 + mt * 16 + (lane >> 2);
            int cc = n0 + wn * 32 + (lane & 3) * 2;
#pragma unroll
            for (int nt = 0; nt < 4; nt++) {
                *(float2*)(C + (size_t)r * N + cc + nt * 8) =
                    make_float2(acc[mt][nt][0], acc[mt][nt][1]);
                *(float2*)(C + (size_t)(r + 8) * N + cc + nt * 8) =
                    make_float2(acc[mt][nt][2], acc[mt][nt][3]);
            }
        }
    }
}

// ---------------- flash attention: R12 + per-warp tile skipping --------------
// smem: Qh 0 | Ql 16384 | Kh 32768 | Kl 40960 | Vh 49152 | Vl 57344 |
//       P 65536 (32768, 256B pitch hi|lo) | kseq 98304
#define ATTN_SMEM 98560

__global__ void __launch_bounds__(256) attn_kernel(const int* __restrict__ seq_id) {
    extern __shared__ __align__(16) char smA[];
    char* Ps = smA + 65536;
    int* kseq = (int*)(smA + 98304);
    uint32_t base = (uint32_t)__cvta_generic_to_shared(smA);
    uint32_t qB = base, kB = base + 32768, vB = base + 49152, pB = base + 65536;

    int qt = blockIdx.x, h = blockIdx.y, b = blockIdx.z;
    int tid = threadIdx.x, wid = tid >> 5, lane = tid & 31;
    int q0 = qt * 128;
    size_t bh = (size_t)(b * H_ + h);
    const int* seqb = seq_id + b * L_;

#pragma unroll
    for (int i = 0; i < 4; i++) {
        int id = tid + i * 256;
        int q = id >> 3, sg = id & 7;
        size_t src = (bh * L_ + q0 + q) * 64 + sg * 8;
        uint32_t ad = qB + q * 128 + ((sg * 16) ^ ((q & 7) << 4));
        cpa16(ad,         g_qh + src);
        cpa16(ad + 16384, g_ql + src);
    }
    cp_commit();

    int qs0 = seqb[q0 + wid * 16 + (lane >> 2)];
    int qs1 = seqb[q0 + wid * 16 + (lane >> 2) + 8];

    auto lbound = [&](int v) {
        int lo = 0, hi = L_;
        while (lo < hi) { int m = (lo + hi) >> 1; if (seqb[m] < v) lo = m + 1; else hi = m; }
        return lo;
    };
    auto ubound = [&](int v) {
        int lo = 0, hi = L_;
        while (lo < hi) { int m = (lo + hi) >> 1; if (seqb[m] <= v) lo = m + 1; else hi = m; }
        return lo;
    };
    // block-level key range
    int kt0 = lbound(seqb[q0]) >> 6;
    int kt1 = (ubound(seqb[q0 + 127]) - 1) >> 6;
    // per-warp key range (rows wid*16 .. wid*16+15)
    int wlo = lbound(seqb[q0 + wid * 16]);
    int whi = ubound(seqb[q0 + wid * 16 + 15]);

    float O[8][4] = {};
    float m0v = -1e30f, m1v = -1e30f, l0s = 0.f, l1s = 0.f;
    int c0 = (lane & 3) * 2;

    for (int kt = kt0; kt <= kt1; kt++) {
        __syncthreads();
#pragma unroll
        for (int i = 0; i < 2; i++) {
            int id = tid + i * 256;
            int kp = id >> 3, sg = id & 7;
            size_t src = (bh * L_ + kt * 64 + kp) * 64 + sg * 8;
            uint32_t sw = (sg * 16) ^ ((kp & 7) << 4);
            cpa16(kB + kp * 128 + sw,        g_kh + src);
            cpa16(kB + kp * 128 + sw + 8192, g_kl + src);
            cpa16(vB + kp * 128 + sw,        g_vh + src);
            cpa16(vB + kp * 128 + sw + 8192, g_vl + src);
        }
        cp_commit();
        if (tid < 64) kseq[tid] = seqb[kt * 64 + tid];
        cp_wait<0>();
        __syncthreads();

        // skip tiles fully outside this warp's segment range: numerically a
        // no-op (all masked -> p=0, alpha=1, l,m,O unchanged) => bit-exact.
        bool active = (kt * 64 < whi) && (kt * 64 + 64 > wlo);
        if (!active) continue;

        // S = Q K^T (3-term)
        float S[8][4] = {};
#pragma unroll
        for (int ds = 0; ds < 4; ds++) {
            uint32_t ah[4], al[4];
            int row = wid * 16 + (lane & 15);
            uint32_t ad = qB + row * 128 +
                          ((ds * 32 + (lane >> 4) * 16) ^ ((row & 7) << 4));
            ldsm4(ad,         ah[0], ah[1], ah[2], ah[3]);
            ldsm4(ad + 16384, al[0], al[1], al[2], al[3]);
#pragma unroll
            for (int np = 0; np < 4; np++) {
                int kpos = (np * 2 + (lane >> 4)) * 8 + (lane & 7);
                int dbyte = ds * 32 + ((lane >> 3) & 1) * 16;
                uint32_t kd = kB + kpos * 128 + (dbyte ^ ((kpos & 7) << 4));
                uint32_t bh0, bh1, bh2, bh3, bl0, bl1, bl2, bl3;
                ldsm4(kd,        bh0, bh1, bh2, bh3);
                ldsm4(kd + 8192, bl0, bl1, bl2, bl3);
                mma16(S[np * 2],     ah, bh0, bh1);
                mma16(S[np * 2],     al, bh0, bh1);
                mma16(S[np * 2],     ah, bl0, bl1);
                mma16(S[np * 2 + 1], ah, bh2, bh3);
                mma16(S[np * 2 + 1], al, bh2, bh3);
                mma16(S[np * 2 + 1], ah, bl2, bl3);
            }
        }
        // mask + scale + online softmax
        float mx0 = -1e30f, mx1 = -1e30f;
#pragma unroll
        for (int nt = 0; nt < 8; nt++) {
            int k0 = kseq[nt * 8 + c0], k1 = kseq[nt * 8 + c0 + 1];
            S[nt][0] = (qs0 == k0) ? S[nt][0] * 0.125f : -1e30f;
            S[nt][1] = (qs0 == k1) ? S[nt][1] * 0.125f : -1e30f;
            S[nt][2] = (qs1 == k0) ? S[nt][2] * 0.125f : -1e30f;
            S[nt][3] = (qs1 == k1) ? S[nt][3] * 0.125f : -1e30f;
            mx0 = fmaxf(mx0, fmaxf(S[nt][0], S[nt][1]));
            mx1 = fmaxf(mx1, fmaxf(S[nt][2], S[nt][3]));
        }
        mx0 = fmaxf(mx0, __shfl_xor_sync(0xffffffffu, mx0, 1));
        mx0 = fmaxf(mx0, __shfl_xor_sync(0xffffffffu, mx0, 2));
        mx1 = fmaxf(mx1, __shfl_xor_sync(0xffffffffu, mx1, 1));
        mx1 = fmaxf(mx1, __shfl_xor_sync(0xffffffffu, mx1, 2));
        float mn0 = fmaxf(m0v, mx0), mn1 = fmaxf(m1v, mx1);
        float al0 = __expf(m0v - mn0), al1 = __expf(m1v - mn1);
        m0v = mn0; m1v = mn1;

        int r = wid * 16 + (lane >> 2);
        int r2 = r + 8;
        float rs0 = 0.f, rs1 = 0.f;
#pragma unroll
        for (int nt = 0; nt < 8; nt++) {
            float p00 = (S[nt][0] <= -9e29f) ? 0.f : __expf(S[nt][0] - mn0);
            float p01 = (S[nt][1] <= -9e29f) ? 0.f : __expf(S[nt][1] - mn0);
            float p10 = (S[nt][2] <= -9e29f) ? 0.f : __expf(S[nt][2] - mn1);
            float p11 = (S[nt][3] <= -9e29f) ? 0.f : __expf(S[nt][3] - mn1);
            rs0 += p00 + p01;
            rs1 += p10 + p11;
            int c = nt * 8 + c0;
            float h00, lo00, h01v, lo01, h10, lo10, h11v, lo11;
            hl(p00, h00, lo00); hl(p01, h01v, lo01);
            hl(p10, h10, lo10); hl(p11, h11v, lo11);
            int sw0 = (c * 2) ^ ((r & 7) << 4);
            char* pp = Ps + r * 256;
            *(uint32_t*)(pp + sw0)       = pk(h00, h01v);
            *(uint32_t*)(pp + 128 + sw0) = pk(lo00, lo01);
            int sw2 = (c * 2) ^ ((r2 & 7) << 4);
            char* pp2 = Ps + r2 * 256;
            *(uint32_t*)(pp2 + sw2)       = pk(h10, h11v);
            *(uint32_t*)(pp2 + 128 + sw2) = pk(lo10, lo11);
        }
        rs0 += __shfl_xor_sync(0xffffffffu, rs0, 1);
        rs0 += __shfl_xor_sync(0xffffffffu, rs0, 2);
        rs1 += __shfl_xor_sync(0xffffffffu, rs1, 1);
        rs1 += __shfl_xor_sync(0xffffffffu, rs1, 2);
        l0s = l0s * al0 + rs0;
        l1s = l1s * al1 + rs1;
#pragma unroll
        for (int nt = 0; nt < 8; nt++) {
            O[nt][0] *= al0; O[nt][1] *= al0;
            O[nt][2] *= al1; O[nt][3] *= al1;
        }
        __syncwarp();

        // O += P V (3-term)
#pragma unroll
        for (int ks = 0; ks < 4; ks++) {
            uint32_t ah[4], al[4];
            int row = wid * 16 + (lane & 15);
            uint32_t ad = pB + row * 256 +
                          ((ks * 32 + (lane >> 4) * 16) ^ ((row & 7) << 4));
            ldsm4(ad,       ah[0], ah[1], ah[2], ah[3]);
            ldsm4(ad + 128, al[0], al[1], al[2], al[3]);
#pragma unroll
            for (int np = 0; np < 4; np++) {
                int kpos = ks * 16 + ((lane >> 3) & 1) * 8 + (lane & 7);
                int dtile = np * 2 + (lane >> 4);
                uint32_t vd = vB + kpos * 128 + ((dtile * 16) ^ ((kpos & 7) << 4));
                uint32_t bh0, bh1, bh2, bh3, bl0, bl1, bl2, bl3;
                ldsm4t(vd,        bh0, bh1, bh2, bh3);
                ldsm4t(vd + 8192, bl0, bl1, bl2, bl3);
                mma16(O[np * 2],     ah, bh0, bh1);
                mma16(O[np * 2],     al, bh0, bh1);
                mma16(O[np * 2],     ah, bl0, bl1);
                mma16(O[np * 2 + 1], ah, bh2, bh3);
                mma16(O[np * 2 + 1], al, bh2, bh3);
                mma16(O[np * 2 + 1], ah, bl2, bl3);
            }
        }
    }
    // epilogue
    float inv0 = 1.0f / l0s, inv1 = 1.0f / l1s;
    int r0 = q0 + wid * 16 + (lane >> 2);
    size_t ob = (bh * L_ + r0) * 64 + (lane & 3) * 2;
#pragma unroll
    for (int nt = 0; nt < 8; nt++) {
        float v0 = O[nt][0] * inv0, v1 = O[nt][1] * inv0;
        float v2 = O[nt][2] * inv1, v3 = O[nt][3] * inv1;
        float h0, lo0, h1, lo1, h2, lo2, h3, lo3;
        hl(v0, h0, lo0); hl(v1, h1, lo1); hl(v2, h2, lo2); hl(v3, h3, lo3);
        *(uint32_t*)(g_ch + ob + nt * 8) = pk(h0, h1);
        *(uint32_t*)(g_cl + ob + nt * 8) = pk(lo0, lo1);
        *(uint32_t*)(g_ch + ob + (size_t)8 * 64 + nt * 8) = pk(h2, h3);
        *(uint32_t*)(g_cl + ob + (size_t)8 * 64 + nt * 8) = pk(lo2, lo3);
    }
}

// ---------------- launch ------------------------------------------------------
extern "C" void kernel_launch(void* const* d_in, const int* in_sizes, int n_in,
                              void* d_out, int out_size) {
    const float* x    = (const float*)d_in[0];
    const int*   seq  = (const int*)d_in[1];
    const float* ln1w = (const float*)d_in[2];
    const float* ln1b = (const float*)d_in[3];
    const float* wqkv = (const float*)d_in[4];
    const float* qlnw = (const float*)d_in[5];
    const float* klnw = (const float*)d_in[6];
    const float* wout = (const float*)d_in[7];
    float* out = (float*)d_out;

    __nv_bfloat16 *hh, *hlp, *wqh, *wql, *woh, *wol, *ch, *cl;
    cudaGetSymbolAddress((void**)&hh,  g_hh);
    cudaGetSymbolAddress((void**)&hlp, g_hl);
    cudaGetSymbolAddress((void**)&wqh, g_wqh);
    cudaGetSymbolAddress((void**)&wql, g_wql);
    cudaGetSymbolAddress((void**)&woh, g_woh);
    cudaGetSymbolAddress((void**)&wol, g_wol);
    cudaGetSymbolAddress((void**)&ch,  g_ch);
    cudaGetSymbolAddress((void**)&cl,  g_cl);
    float* qkvp;
    cudaGetSymbolAddress((void**)&qkvp, g_qkv);

    cudaFuncSetAttribute((const void*)gemm_tc<false, true>,
                         cudaFuncAttributeMaxDynamicSharedMemorySize, GEMM_SMEM);
    cudaFuncSetAttribute((const void*)gemm_tc<true, false>,
                         cudaFuncAttributeMaxDynamicSharedMemorySize, GEMM_SMEM);
    cudaFuncSetAttribute(attn_kernel,
                         cudaFuncAttributeMaxDynamicSharedMemorySize, ATTN_SMEM);

    rope_tab_kernel<<<L_, 32>>>();
    convw_kernel<<<(D_ * D3_ / 4 + 255) / 256, 256>>>(wqkv, wqh, wql, D_ * D3_ / 4);
    convw_kernel<<<(D_ * D_ / 4 + 255) / 256, 256>>>(wout, woh, wol, D_ * D_ / 4);
    ln1_kernel<<<R_, 256>>>(x, ln1w, ln1b);
    gemm_tc<false, true><<<dim3(D3_ / 64, R_ / 128), 256, GEMM_SMEM>>>(
        hh, hlp, wqh, wql, qkvp, D3_);
    qkln_rope_kernel<<<dim3(R_, 2), 256>>>(qlnw, klnw);
    attn_kernel<<<dim3(L_ / 128, H_, B_), 256, ATTN_SMEM>>>(seq);
    gemm_tc<true, false><<<dim3(D_ / 64, R_ / 128), 256, GEMM_SMEM>>>(
        ch, cl, woh, wol, out, D_);
}